// round 8
// baseline (speedup 1.0000x reference)
#include <cuda_runtime.h>
#include <math.h>

// Problem constants: B=8, N=8192, C=256, K=8, nblocks=8, blk=32
#define TOK_TOTAL 65536          // B*N
#define N_TOK     8192
#define C_DIM     256
#define K_NB      8
#define EPS_W     0.05f
#define OME_W     0.95f

// Scratch (allocation-free rule: __device__ globals)
__device__ float g_t[(size_t)TOK_TOTAL * C_DIM];   // 64 MB monarch output
__device__ float g_w[(size_t)TOK_TOTAL * K_NB];    // eps-scaled softmax weights

// ---- packed f32x2 helpers (FFMA2: ptxas never auto-fuses; PTX-only) --------
union F2U { float2 f; unsigned long long u; };

__device__ __forceinline__ unsigned long long pk2(float x, float y) {
    F2U t; t.f.x = x; t.f.y = y; return t.u;
}
__device__ __forceinline__ void ffma2(unsigned long long& d,
                                      unsigned long long a,
                                      unsigned long long b) {
    asm("fma.rn.f32x2 %0, %1, %2, %0;" : "+l"(d) : "l"(a), "l"(b));
}
__device__ __forceinline__ float hsum2(unsigned long long v) {
    F2U t; t.u = v; return t.f.x + t.f.y;
}

// ---------------------------------------------------------------------------
// Kernel 0: per-token eps*softmax(-distance). d in [0,1) -> exp(-d) in [.37,1]
// so no max-subtraction needed; __expf (MUFU) is plenty accurate.
// ---------------------------------------------------------------------------
__global__ void softmax_k(const float* __restrict__ dist) {
    int tok = blockIdx.x * blockDim.x + threadIdx.x;
    if (tok >= TOK_TOTAL) return;
    const float4* dp = (const float4*)(dist + (size_t)tok * K_NB);
    float4 a = dp[0], b4 = dp[1];
    float d[8] = {a.x, a.y, a.z, a.w, b4.x, b4.y, b4.z, b4.w};
    float e[8];
    float s = 0.f;
#pragma unroll
    for (int k = 0; k < 8; k++) { e[k] = __expf(-d[k]); s += e[k]; }
    float inv = EPS_W / s;
    float4* wp = (float4*)(g_w + (size_t)tok * K_NB);
    wp[0] = make_float4(e[0]*inv, e[1]*inv, e[2]*inv, e[3]*inv);
    wp[1] = make_float4(e[4]*inv, e[5]*inv, e[6]*inv, e[7]*inv);
}

// ---------------------------------------------------------------------------
// Kernel 1: fused rectify1 + monarch, software pipelined, f32x2 math.
// 256 threads, 4 tokens per round, 8 rounds per block (32 tokens, 2048 blocks).
// __launch_bounds__(256,1): 255-reg budget so the 9-float4 prefetch stays in
// registers (at (256,2) it spilled, killing the pipeline).
// ---------------------------------------------------------------------------
__global__ void __launch_bounds__(256, 1) k1_rect_monarch(
        const float* __restrict__ x,
        const int*   __restrict__ idx,
        const float* __restrict__ w1,
        const float* __restrict__ w2,
        const float* __restrict__ bias) {
    __shared__ __align__(16) float sv[2][4][C_DIM];
    __shared__ __align__(16) float so1[4][288];     // 8 * 36 padded

    const int tid = threadIdx.x;

    // Per-thread monarch weight rows, pre-packed as f32x2 pairs along the
    // reduction dimension (p for stage1, r for stage2).
    unsigned long long w1p[16], w2p[16];
    {
        const float4* p1 = (const float4*)(w1 + (size_t)tid * 32);
#pragma unroll
        for (int i = 0; i < 8; i++) {
            float4 f = p1[i];
            w1p[2*i+0] = pk2(f.x, f.y);
            w1p[2*i+1] = pk2(f.z, f.w);
        }
        const float4* p2 = (const float4*)(w2 + (size_t)(tid & 7) * 1024 + (size_t)(tid >> 3) * 32);
#pragma unroll
        for (int i = 0; i < 8; i++) {
            float4 f = p2[i];
            w2p[2*i+0] = pk2(f.x, f.y);
            w2p[2*i+1] = pk2(f.z, f.w);
        }
    }
    const float br = bias[tid];
    const unsigned long long omep = pk2(OME_W, OME_W);

    const int t = tid >> 6;          // token-in-round 0..3
    const int q = tid & 63;          // float4 quad 0..63
    const int tokBlock = blockIdx.x * 32;            // 32 tokens per block
    const int b = tokBlock >> 13;                    // batch (N=8192)
    const float* xb = x + ((size_t)b << 13) * C_DIM; // batch base for gathers

    const int kbase = tid & 0xE0;                    // stage1 input block base
    const int widx  = (tid & 7) * 36 + (tid >> 3);   // transposed o1 slot
    const int lbase = (tid & 7) * 36;                // stage2 input row base

    // ---- Prefetch round 0: weights (dup-packed), idx, gather rows
    float4 v[9];
    unsigned long long swp[8];
    int offs[8];
    {
        const int tok = tokBlock + t;
        const float4* wp = (const float4*)(g_w + (size_t)tok * 8);
        float4 wa = wp[0], wb = wp[1];
        swp[0]=pk2(wa.x,wa.x); swp[1]=pk2(wa.y,wa.y); swp[2]=pk2(wa.z,wa.z); swp[3]=pk2(wa.w,wa.w);
        swp[4]=pk2(wb.x,wb.x); swp[5]=pk2(wb.y,wb.y); swp[6]=pk2(wb.z,wb.z); swp[7]=pk2(wb.w,wb.w);
        const int4* ip = (const int4*)(idx + (size_t)tok * 8);
        int4 ia = ip[0], ib = ip[1];
        offs[0]=ia.x*C_DIM; offs[1]=ia.y*C_DIM; offs[2]=ia.z*C_DIM; offs[3]=ia.w*C_DIM;
        offs[4]=ib.x*C_DIM; offs[5]=ib.y*C_DIM; offs[6]=ib.z*C_DIM; offs[7]=ib.w*C_DIM;
        v[0] = ((const float4*)(x + (size_t)tok * C_DIM))[q];
#pragma unroll
        for (int k = 0; k < 8; k++)
            v[k+1] = ((const float4*)(xb + offs[k]))[q];
    }

#pragma unroll 1
    for (int r = 0; r < 8; r++) {
        const int buf  = r & 1;
        const int tok0 = tokBlock + r * 4;

        // ---- Consume prefetched gather into the weighted sum; stage to smem
        {
            unsigned long long a01 = 0ull, a23 = 0ull;   // (0.f,0.f)
            ffma2(a01, omep, pk2(v[0].x, v[0].y));
            ffma2(a23, omep, pk2(v[0].z, v[0].w));
#pragma unroll
            for (int k = 0; k < 8; k++) {
                ffma2(a01, swp[k], pk2(v[k+1].x, v[k+1].y));
                ffma2(a23, swp[k], pk2(v[k+1].z, v[k+1].w));
            }
            F2U lo, hi; lo.u = a01; hi.u = a23;
            ((float4*)sv[buf][t])[q] = make_float4(lo.f.x, lo.f.y, hi.f.x, hi.f.y);
        }

        // ---- Issue next round's prefetch (overlaps with phases B+C below)
        if (r < 7) {
            const int tok = tok0 + 4 + t;
            const float4* wp = (const float4*)(g_w + (size_t)tok * 8);
            float4 wa = wp[0], wb = wp[1];
            swp[0]=pk2(wa.x,wa.x); swp[1]=pk2(wa.y,wa.y); swp[2]=pk2(wa.z,wa.z); swp[3]=pk2(wa.w,wa.w);
            swp[4]=pk2(wb.x,wb.x); swp[5]=pk2(wb.y,wb.y); swp[6]=pk2(wb.z,wb.z); swp[7]=pk2(wb.w,wb.w);
            const int4* ip = (const int4*)(idx + (size_t)tok * 8);
            int4 ia = ip[0], ib = ip[1];
            offs[0]=ia.x*C_DIM; offs[1]=ia.y*C_DIM; offs[2]=ia.z*C_DIM; offs[3]=ia.w*C_DIM;
            offs[4]=ib.x*C_DIM; offs[5]=ib.y*C_DIM; offs[6]=ib.z*C_DIM; offs[7]=ib.w*C_DIM;
            v[0] = ((const float4*)(x + (size_t)tok * C_DIM))[q];
#pragma unroll
            for (int k = 0; k < 8; k++)
                v[k+1] = ((const float4*)(xb + offs[k]))[q];
        }

        __syncthreads();   // sv[buf] visible; C(r-1) done reading so1

        // ---- Phase B: stage1 (o1[k*32+q] = sum_p w1[k,q,p] * v[k*32+p])
        // f32x2 pairs along p; one horizontal add per output.
#pragma unroll
        for (int tt = 0; tt < 4; tt++) {
            const float4* vp = (const float4*)(&sv[buf][tt][kbase]);
            unsigned long long acc = 0ull;
#pragma unroll
            for (int p = 0; p < 8; p++) {
                float4 f = vp[p];
                ffma2(acc, w1p[2*p+0], pk2(f.x, f.y));
                ffma2(acc, w1p[2*p+1], pk2(f.z, f.w));
            }
            so1[tt][widx] = hsum2(acc);   // transposed: f=tid -> (l=f&7, r=f>>3)
        }
        __syncthreads();

        // ---- Phase C: stage2 (out[s*8+l] = sum_r w2[l,s,r] * o1[r*8+l] + bias)
#pragma unroll
        for (int tt = 0; tt < 4; tt++) {
            const float4* op = (const float4*)(&so1[tt][lbase]);
            unsigned long long acc = pk2(br, 0.f);
#pragma unroll
            for (int p = 0; p < 8; p++) {
                float4 f = op[p];
                ffma2(acc, w2p[2*p+0], pk2(f.x, f.y));
                ffma2(acc, w2p[2*p+1], pk2(f.z, f.w));
            }
            g_t[(size_t)(tok0 + tt) * C_DIM + tid] = hsum2(acc);
        }
        // no trailing barrier: next round's sv store targets the other buffer,
        // and barrier1 of the next round protects so1 against its next writer.
    }
}

// ---------------------------------------------------------------------------
// Kernel 2: rectify2 on t + rf. WARP-PER-TOKEN, barrier-free.
// Lane handles float4 quads {lane, lane+32}; weights/idx broadcast via shfl.
// ---------------------------------------------------------------------------
__global__ void __launch_bounds__(256) k2_rect_add(
        const float* __restrict__ rf,
        const int*   __restrict__ idx,
        float*       __restrict__ out) {
    const int lane = threadIdx.x & 31;
    const int warp = threadIdx.x >> 5;
    const int tok  = blockIdx.x * 8 + warp;     // grid = TOK_TOTAL/8
    const int b    = tok >> 13;
    const float* tb = g_t + ((size_t)b << 13) * C_DIM;

    // lanes 0-7 fetch this token's weights and neighbor indices
    float wv = 0.f; int iv = 0;
    if (lane < 8) {
        wv = g_w[(size_t)tok * 8 + lane];
        iv = idx[(size_t)tok * 8 + lane];
    }

    const float4* trow = (const float4*)(g_t + (size_t)tok * C_DIM);
    float4 s0 = trow[lane], s1 = trow[lane + 32];
    const float4* rrow = (const float4*)(rf + (size_t)tok * C_DIM);
    float4 r0 = rrow[lane], r1 = rrow[lane + 32];

    float4 a0 = make_float4(OME_W*s0.x + r0.x, OME_W*s0.y + r0.y,
                            OME_W*s0.z + r0.z, OME_W*s0.w + r0.w);
    float4 a1 = make_float4(OME_W*s1.x + r1.x, OME_W*s1.y + r1.y,
                            OME_W*s1.z + r1.z, OME_W*s1.w + r1.w);

#pragma unroll
    for (int k = 0; k < 8; k++) {
        float wk = __shfl_sync(0xFFFFFFFFu, wv, k);
        int   nb = __shfl_sync(0xFFFFFFFFu, iv, k);
        const float4* nr = (const float4*)(tb + (size_t)nb * C_DIM);
        float4 n0 = nr[lane], n1 = nr[lane + 32];
        a0.x = fmaf(wk, n0.x, a0.x);  a0.y = fmaf(wk, n0.y, a0.y);
        a0.z = fmaf(wk, n0.z, a0.z);  a0.w = fmaf(wk, n0.w, a0.w);
        a1.x = fmaf(wk, n1.x, a1.x);  a1.y = fmaf(wk, n1.y, a1.y);
        a1.z = fmaf(wk, n1.z, a1.z);  a1.w = fmaf(wk, n1.w, a1.w);
    }

    float4* orow = (float4*)(out + (size_t)tok * C_DIM);
    orow[lane]      = a0;
    orow[lane + 32] = a1;
}

// ---------------------------------------------------------------------------
extern "C" void kernel_launch(void* const* d_in, const int* in_sizes, int n_in,
                              void* d_out, int out_size) {
    const float* x    = (const float*)d_in[0];
    const float* dist = (const float*)d_in[1];
    const int*   idx  = (const int*)  d_in[2];
    const float* rf   = (const float*)d_in[3];
    const float* w1   = (const float*)d_in[4];
    const float* w2   = (const float*)d_in[5];
    const float* bias = (const float*)d_in[6];
    float* out = (float*)d_out;

    softmax_k<<<TOK_TOTAL / 256, 256>>>(dist);
    k1_rect_monarch<<<TOK_TOTAL / 32, 256>>>(x, idx, w1, w2, bias);
    k2_rect_add<<<TOK_TOTAL / 8, 256>>>(rf, idx, out);
}

// round 9
// speedup vs baseline: 1.0024x; 1.0024x over previous
#include <cuda_runtime.h>
#include <math.h>

// Problem constants: B=8, N=8192, C=256, K=8, nblocks=8, blk=32
#define TOK_TOTAL 65536          // B*N
#define N_TOK     8192
#define C_DIM     256
#define K_NB      8
#define EPS_W     0.05f
#define OME_W     0.95f

// Scratch (allocation-free rule: __device__ globals)
__device__ float g_t[(size_t)TOK_TOTAL * C_DIM];   // 64 MB monarch output
__device__ float g_w[(size_t)TOK_TOTAL * K_NB];    // eps-scaled softmax weights

// ---- packed f32x2 helpers (FFMA2: ptxas never auto-fuses; PTX-only) --------
union F2U { float2 f; unsigned long long u; };

__device__ __forceinline__ unsigned long long pk2(float x, float y) {
    F2U t; t.f.x = x; t.f.y = y; return t.u;
}
__device__ __forceinline__ void ffma2(unsigned long long& d,
                                      unsigned long long a,
                                      unsigned long long b) {
    asm("fma.rn.f32x2 %0, %1, %2, %0;" : "+l"(d) : "l"(a), "l"(b));
}
__device__ __forceinline__ float hsum2(unsigned long long v) {
    F2U t; t.u = v; return t.f.x + t.f.y;
}

// ---------------------------------------------------------------------------
// Kernel 0: per-token eps*softmax(-distance). d in [0,1) -> exp(-d) in [.37,1]
// so no max-subtraction needed; __expf (MUFU) is plenty accurate.
// ---------------------------------------------------------------------------
__global__ void softmax_k(const float* __restrict__ dist) {
    int tok = blockIdx.x * blockDim.x + threadIdx.x;
    if (tok >= TOK_TOTAL) return;
    const float4* dp = (const float4*)(dist + (size_t)tok * K_NB);
    float4 a = dp[0], b4 = dp[1];
    float d[8] = {a.x, a.y, a.z, a.w, b4.x, b4.y, b4.z, b4.w};
    float e[8];
    float s = 0.f;
#pragma unroll
    for (int k = 0; k < 8; k++) { e[k] = __expf(-d[k]); s += e[k]; }
    float inv = EPS_W / s;
    float4* wp = (float4*)(g_w + (size_t)tok * K_NB);
    wp[0] = make_float4(e[0]*inv, e[1]*inv, e[2]*inv, e[3]*inv);
    wp[1] = make_float4(e[4]*inv, e[5]*inv, e[6]*inv, e[7]*inv);
}

// ---------------------------------------------------------------------------
// Kernel 1: fused rectify1 + monarch, software pipelined, f32x2 math.
// 256 threads, 4 tokens per round, 8 rounds per block (32 tokens, 2048 blocks).
// __launch_bounds__(256,1): 255-reg budget so the 9-float4 prefetch stays in
// registers (at (256,2) it spilled, killing the pipeline).
// ---------------------------------------------------------------------------
__global__ void __launch_bounds__(256, 1) k1_rect_monarch(
        const float* __restrict__ x,
        const int*   __restrict__ idx,
        const float* __restrict__ w1,
        const float* __restrict__ w2,
        const float* __restrict__ bias) {
    __shared__ __align__(16) float sv[2][4][C_DIM];
    __shared__ __align__(16) float so1[4][288];     // 8 * 36 padded

    const int tid = threadIdx.x;

    // Per-thread monarch weight rows, pre-packed as f32x2 pairs along the
    // reduction dimension (p for stage1, r for stage2).
    unsigned long long w1p[16], w2p[16];
    {
        const float4* p1 = (const float4*)(w1 + (size_t)tid * 32);
#pragma unroll
        for (int i = 0; i < 8; i++) {
            float4 f = p1[i];
            w1p[2*i+0] = pk2(f.x, f.y);
            w1p[2*i+1] = pk2(f.z, f.w);
        }
        const float4* p2 = (const float4*)(w2 + (size_t)(tid & 7) * 1024 + (size_t)(tid >> 3) * 32);
#pragma unroll
        for (int i = 0; i < 8; i++) {
            float4 f = p2[i];
            w2p[2*i+0] = pk2(f.x, f.y);
            w2p[2*i+1] = pk2(f.z, f.w);
        }
    }
    const float br = bias[tid];
    const unsigned long long omep = pk2(OME_W, OME_W);

    const int t = tid >> 6;          // token-in-round 0..3
    const int q = tid & 63;          // float4 quad 0..63
    const int tokBlock = blockIdx.x * 32;            // 32 tokens per block
    const int b = tokBlock >> 13;                    // batch (N=8192)
    const float* xb = x + ((size_t)b << 13) * C_DIM; // batch base for gathers

    const int kbase = tid & 0xE0;                    // stage1 input block base
    const int widx  = (tid & 7) * 36 + (tid >> 3);   // transposed o1 slot
    const int lbase = (tid & 7) * 36;                // stage2 input row base

    // ---- Prefetch round 0: weights (dup-packed), idx, gather rows
    float4 v[9];
    unsigned long long swp[8];
    int offs[8];
    {
        const int tok = tokBlock + t;
        const float4* wp = (const float4*)(g_w + (size_t)tok * 8);
        float4 wa = wp[0], wb = wp[1];
        swp[0]=pk2(wa.x,wa.x); swp[1]=pk2(wa.y,wa.y); swp[2]=pk2(wa.z,wa.z); swp[3]=pk2(wa.w,wa.w);
        swp[4]=pk2(wb.x,wb.x); swp[5]=pk2(wb.y,wb.y); swp[6]=pk2(wb.z,wb.z); swp[7]=pk2(wb.w,wb.w);
        const int4* ip = (const int4*)(idx + (size_t)tok * 8);
        int4 ia = ip[0], ib = ip[1];
        offs[0]=ia.x*C_DIM; offs[1]=ia.y*C_DIM; offs[2]=ia.z*C_DIM; offs[3]=ia.w*C_DIM;
        offs[4]=ib.x*C_DIM; offs[5]=ib.y*C_DIM; offs[6]=ib.z*C_DIM; offs[7]=ib.w*C_DIM;
        v[0] = ((const float4*)(x + (size_t)tok * C_DIM))[q];
#pragma unroll
        for (int k = 0; k < 8; k++)
            v[k+1] = ((const float4*)(xb + offs[k]))[q];
    }

#pragma unroll 1
    for (int r = 0; r < 8; r++) {
        const int buf  = r & 1;
        const int tok0 = tokBlock + r * 4;

        // ---- Consume prefetched gather into the weighted sum; stage to smem
        {
            unsigned long long a01 = 0ull, a23 = 0ull;   // (0.f,0.f)
            ffma2(a01, omep, pk2(v[0].x, v[0].y));
            ffma2(a23, omep, pk2(v[0].z, v[0].w));
#pragma unroll
            for (int k = 0; k < 8; k++) {
                ffma2(a01, swp[k], pk2(v[k+1].x, v[k+1].y));
                ffma2(a23, swp[k], pk2(v[k+1].z, v[k+1].w));
            }
            F2U lo, hi; lo.u = a01; hi.u = a23;
            ((float4*)sv[buf][t])[q] = make_float4(lo.f.x, lo.f.y, hi.f.x, hi.f.y);
        }

        // ---- Issue next round's prefetch (overlaps with phases B+C below)
        if (r < 7) {
            const int tok = tok0 + 4 + t;
            const float4* wp = (const float4*)(g_w + (size_t)tok * 8);
            float4 wa = wp[0], wb = wp[1];
            swp[0]=pk2(wa.x,wa.x); swp[1]=pk2(wa.y,wa.y); swp[2]=pk2(wa.z,wa.z); swp[3]=pk2(wa.w,wa.w);
            swp[4]=pk2(wb.x,wb.x); swp[5]=pk2(wb.y,wb.y); swp[6]=pk2(wb.z,wb.z); swp[7]=pk2(wb.w,wb.w);
            const int4* ip = (const int4*)(idx + (size_t)tok * 8);
            int4 ia = ip[0], ib = ip[1];
            offs[0]=ia.x*C_DIM; offs[1]=ia.y*C_DIM; offs[2]=ia.z*C_DIM; offs[3]=ia.w*C_DIM;
            offs[4]=ib.x*C_DIM; offs[5]=ib.y*C_DIM; offs[6]=ib.z*C_DIM; offs[7]=ib.w*C_DIM;
            v[0] = ((const float4*)(x + (size_t)tok * C_DIM))[q];
#pragma unroll
            for (int k = 0; k < 8; k++)
                v[k+1] = ((const float4*)(xb + offs[k]))[q];
        }

        __syncthreads();   // sv[buf] visible; C(r-1) done reading so1

        // ---- Phase B: stage1 (o1[k*32+q] = sum_p w1[k,q,p] * v[k*32+p])
        // f32x2 pairs along p; one horizontal add per output.
#pragma unroll
        for (int tt = 0; tt < 4; tt++) {
            const float4* vp = (const float4*)(&sv[buf][tt][kbase]);
            unsigned long long acc = 0ull;
#pragma unroll
            for (int p = 0; p < 8; p++) {
                float4 f = vp[p];
                ffma2(acc, w1p[2*p+0], pk2(f.x, f.y));
                ffma2(acc, w1p[2*p+1], pk2(f.z, f.w));
            }
            so1[tt][widx] = hsum2(acc);   // transposed: f=tid -> (l=f&7, r=f>>3)
        }
        __syncthreads();

        // ---- Phase C: stage2 (out[s*8+l] = sum_r w2[l,s,r] * o1[r*8+l] + bias)
#pragma unroll
        for (int tt = 0; tt < 4; tt++) {
            const float4* op = (const float4*)(&so1[tt][lbase]);
            unsigned long long acc = pk2(br, 0.f);
#pragma unroll
            for (int p = 0; p < 8; p++) {
                float4 f = op[p];
                ffma2(acc, w2p[2*p+0], pk2(f.x, f.y));
                ffma2(acc, w2p[2*p+1], pk2(f.z, f.w));
            }
            g_t[(size_t)(tok0 + tt) * C_DIM + tid] = hsum2(acc);
        }
        // no trailing barrier: next round's sv store targets the other buffer,
        // and barrier1 of the next round protects so1 against its next writer.
    }
}

// ---------------------------------------------------------------------------
// Kernel 2: rectify2 on t + rf. WARP-PER-TOKEN, barrier-free.
// Lane handles float4 quads {lane, lane+32}; weights/idx broadcast via shfl.
// ---------------------------------------------------------------------------
__global__ void __launch_bounds__(256) k2_rect_add(
        const float* __restrict__ rf,
        const int*   __restrict__ idx,
        float*       __restrict__ out) {
    const int lane = threadIdx.x & 31;
    const int warp = threadIdx.x >> 5;
    const int tok  = blockIdx.x * 8 + warp;     // grid = TOK_TOTAL/8
    const int b    = tok >> 13;
    const float* tb = g_t + ((size_t)b << 13) * C_DIM;

    // lanes 0-7 fetch this token's weights and neighbor indices
    float wv = 0.f; int iv = 0;
    if (lane < 8) {
        wv = g_w[(size_t)tok * 8 + lane];
        iv = idx[(size_t)tok * 8 + lane];
    }

    const float4* trow = (const float4*)(g_t + (size_t)tok * C_DIM);
    float4 s0 = trow[lane], s1 = trow[lane + 32];
    const float4* rrow = (const float4*)(rf + (size_t)tok * C_DIM);
    float4 r0 = rrow[lane], r1 = rrow[lane + 32];

    float4 a0 = make_float4(OME_W*s0.x + r0.x, OME_W*s0.y + r0.y,
                            OME_W*s0.z + r0.z, OME_W*s0.w + r0.w);
    float4 a1 = make_float4(OME_W*s1.x + r1.x, OME_W*s1.y + r1.y,
                            OME_W*s1.z + r1.z, OME_W*s1.w + r1.w);

#pragma unroll
    for (int k = 0; k < 8; k++) {
        float wk = __shfl_sync(0xFFFFFFFFu, wv, k);
        int   nb = __shfl_sync(0xFFFFFFFFu, iv, k);
        const float4* nr = (const float4*)(tb + (size_t)nb * C_DIM);
        float4 n0 = nr[lane], n1 = nr[lane + 32];
        a0.x = fmaf(wk, n0.x, a0.x);  a0.y = fmaf(wk, n0.y, a0.y);
        a0.z = fmaf(wk, n0.z, a0.z);  a0.w = fmaf(wk, n0.w, a0.w);
        a1.x = fmaf(wk, n1.x, a1.x);  a1.y = fmaf(wk, n1.y, a1.y);
        a1.z = fmaf(wk, n1.z, a1.z);  a1.w = fmaf(wk, n1.w, a1.w);
    }

    float4* orow = (float4*)(out + (size_t)tok * C_DIM);
    orow[lane]      = a0;
    orow[lane + 32] = a1;
}

// ---------------------------------------------------------------------------
extern "C" void kernel_launch(void* const* d_in, const int* in_sizes, int n_in,
                              void* d_out, int out_size) {
    const float* x    = (const float*)d_in[0];
    const float* dist = (const float*)d_in[1];
    const int*   idx  = (const int*)  d_in[2];
    const float* rf   = (const float*)d_in[3];
    const float* w1   = (const float*)d_in[4];
    const float* w2   = (const float*)d_in[5];
    const float* bias = (const float*)d_in[6];
    float* out = (float*)d_out;

    softmax_k<<<TOK_TOTAL / 256, 256>>>(dist);
    k1_rect_monarch<<<TOK_TOTAL / 32, 256>>>(x, idx, w1, w2, bias);
    k2_rect_add<<<TOK_TOTAL / 8, 256>>>(rf, idx, out);
}

// round 10
// speedup vs baseline: 1.1555x; 1.1527x over previous
#include <cuda_runtime.h>
#include <cuda_bf16.h>
#include <math.h>

// Problem constants: B=8, N=8192, C=256, K=8, nblocks=8, blk=32
#define TOK_TOTAL 65536          // B*N
#define N_TOK     8192
#define C_DIM     256
#define K_NB      8
#define EPS_W     0.05f
#define OME_W     0.95f

// Scratch (allocation-free rule: __device__ globals)
__device__ float          g_t [(size_t)TOK_TOTAL * C_DIM];  // 64 MB monarch out (f32)
__device__ __nv_bfloat16  g_th[(size_t)TOK_TOTAL * C_DIM];  // 32 MB bf16 shadow of t
__device__ __nv_bfloat16  g_xh[(size_t)TOK_TOTAL * C_DIM];  // 32 MB bf16 shadow of x
__device__ float          g_w [(size_t)TOK_TOTAL * K_NB];   // eps-scaled softmax weights

// bf16 -> f32 is exact: just a shift/mask into the high mantissa bits (ALU pipe).
__device__ __forceinline__ float bf_lo(unsigned u) { return __uint_as_float(u << 16); }
__device__ __forceinline__ float bf_hi(unsigned u) { return __uint_as_float(u & 0xFFFF0000u); }

// ---------------------------------------------------------------------------
// Kernel 0 (prep): blocks [0,256) compute eps*softmax(-distance);
// blocks [256, 256+16384) convert x (f32) -> g_xh (bf16), float4 granularity.
// d in [0,1) -> exp(-d) in [.37,1]: no max pass needed, __expf suffices.
// ---------------------------------------------------------------------------
__global__ void prep_k(const float* __restrict__ dist, const float* __restrict__ x) {
    if (blockIdx.x < 256) {
        int tok = blockIdx.x * blockDim.x + threadIdx.x;
        const float4* dp = (const float4*)(dist + (size_t)tok * K_NB);
        float4 a = dp[0], b4 = dp[1];
        float d[8] = {a.x, a.y, a.z, a.w, b4.x, b4.y, b4.z, b4.w};
        float e[8];
        float s = 0.f;
#pragma unroll
        for (int k = 0; k < 8; k++) { e[k] = __expf(-d[k]); s += e[k]; }
        float inv = EPS_W / s;
        float4* wp = (float4*)(g_w + (size_t)tok * K_NB);
        wp[0] = make_float4(e[0]*inv, e[1]*inv, e[2]*inv, e[3]*inv);
        wp[1] = make_float4(e[4]*inv, e[5]*inv, e[6]*inv, e[7]*inv);
    } else {
        size_t i = (size_t)(blockIdx.x - 256) * blockDim.x + threadIdx.x; // float4 id
        float4 f = ((const float4*)x)[i];
        __nv_bfloat162 h0 = __float22bfloat162_rn(make_float2(f.x, f.y));
        __nv_bfloat162 h1 = __float22bfloat162_rn(make_float2(f.z, f.w));
        uint2 o;
        o.x = *reinterpret_cast<unsigned*>(&h0);
        o.y = *reinterpret_cast<unsigned*>(&h1);
        ((uint2*)g_xh)[i] = o;
    }
}

// ---------------------------------------------------------------------------
// Kernel 1: fused rectify1 + monarch, software pipelined, bf16 gathers.
// 256 threads, 4 tokens/round, 8 rounds/block (32 tokens, 2048 blocks).
// bf16 prefetch (uint2 x8 = 16 regs) keeps the pipeline register-resident at
// occ=2 (round 2 spilled with f32 prefetch; round 9 showed occ=1 is too low).
// ---------------------------------------------------------------------------
__global__ void __launch_bounds__(256, 2) k1_rect_monarch(
        const float* __restrict__ x,
        const int*   __restrict__ idx,
        const float* __restrict__ w1,
        const float* __restrict__ w2,
        const float* __restrict__ bias) {
    __shared__ __align__(16) float sv[2][4][C_DIM];
    __shared__ __align__(16) float so1[4][288];     // 8 * 36 padded

    const int tid = threadIdx.x;

    // Per-thread monarch weight rows (register resident, scalar FMA path)
    float w1r[32], w2r[32];
    {
        const float4* p1 = (const float4*)(w1 + (size_t)tid * 32);
#pragma unroll
        for (int i = 0; i < 8; i++) {
            float4 f = p1[i];
            w1r[4*i+0] = f.x; w1r[4*i+1] = f.y; w1r[4*i+2] = f.z; w1r[4*i+3] = f.w;
        }
        const float4* p2 = (const float4*)(w2 + (size_t)(tid & 7) * 1024 + (size_t)(tid >> 3) * 32);
#pragma unroll
        for (int i = 0; i < 8; i++) {
            float4 f = p2[i];
            w2r[4*i+0] = f.x; w2r[4*i+1] = f.y; w2r[4*i+2] = f.z; w2r[4*i+3] = f.w;
        }
    }
    const float br = bias[tid];

    const int t = tid >> 6;          // token-in-round 0..3
    const int q = tid & 63;          // float4 / uint2 quad 0..63
    const int tokBlock = blockIdx.x * 32;            // 32 tokens per block
    const int b = tokBlock >> 13;                    // batch (N=8192)
    const __nv_bfloat16* xhb = g_xh + ((size_t)b << 13) * C_DIM; // bf16 gather base

    const int kbase = tid & 0xE0;                    // stage1 input block base
    const int widx  = (tid & 7) * 36 + (tid >> 3);   // transposed o1 slot
    const int lbase = (tid & 7) * 36;                // stage2 input row base

    // ---- Prefetch round 0: weights, idx, self (f32) + neighbors (bf16)
    float4 vself;
    uint2  v[8];
    float  swr[8];
    {
        const int tok = tokBlock + t;
        const float4* wp = (const float4*)(g_w + (size_t)tok * 8);
        float4 wa = wp[0], wb = wp[1];
        swr[0]=wa.x; swr[1]=wa.y; swr[2]=wa.z; swr[3]=wa.w;
        swr[4]=wb.x; swr[5]=wb.y; swr[6]=wb.z; swr[7]=wb.w;
        const int4* ip = (const int4*)(idx + (size_t)tok * 8);
        int4 ia = ip[0], ib = ip[1];
        vself = ((const float4*)(x + (size_t)tok * C_DIM))[q];
        v[0] = ((const uint2*)(xhb + (size_t)ia.x * C_DIM))[q];
        v[1] = ((const uint2*)(xhb + (size_t)ia.y * C_DIM))[q];
        v[2] = ((const uint2*)(xhb + (size_t)ia.z * C_DIM))[q];
        v[3] = ((const uint2*)(xhb + (size_t)ia.w * C_DIM))[q];
        v[4] = ((const uint2*)(xhb + (size_t)ib.x * C_DIM))[q];
        v[5] = ((const uint2*)(xhb + (size_t)ib.y * C_DIM))[q];
        v[6] = ((const uint2*)(xhb + (size_t)ib.z * C_DIM))[q];
        v[7] = ((const uint2*)(xhb + (size_t)ib.w * C_DIM))[q];
    }

#pragma unroll 1
    for (int r = 0; r < 8; r++) {
        const int buf  = r & 1;
        const int tok0 = tokBlock + r * 4;

        // ---- Consume prefetched gather into the weighted sum; stage to smem
        {
            float4 acc = make_float4(OME_W*vself.x, OME_W*vself.y,
                                     OME_W*vself.z, OME_W*vself.w);
#pragma unroll
            for (int k = 0; k < 8; k++) {
                float wk = swr[k];
                acc.x = fmaf(wk, bf_lo(v[k].x), acc.x);
                acc.y = fmaf(wk, bf_hi(v[k].x), acc.y);
                acc.z = fmaf(wk, bf_lo(v[k].y), acc.z);
                acc.w = fmaf(wk, bf_hi(v[k].y), acc.w);
            }
            ((float4*)sv[buf][t])[q] = acc;
        }

        // ---- Issue next round's prefetch (overlaps with phases B+C below)
        if (r < 7) {
            const int tok = tok0 + 4 + t;
            const float4* wp = (const float4*)(g_w + (size_t)tok * 8);
            float4 wa = wp[0], wb = wp[1];
            swr[0]=wa.x; swr[1]=wa.y; swr[2]=wa.z; swr[3]=wa.w;
            swr[4]=wb.x; swr[5]=wb.y; swr[6]=wb.z; swr[7]=wb.w;
            const int4* ip = (const int4*)(idx + (size_t)tok * 8);
            int4 ia = ip[0], ib = ip[1];
            vself = ((const float4*)(x + (size_t)tok * C_DIM))[q];
            v[0] = ((const uint2*)(xhb + (size_t)ia.x * C_DIM))[q];
            v[1] = ((const uint2*)(xhb + (size_t)ia.y * C_DIM))[q];
            v[2] = ((const uint2*)(xhb + (size_t)ia.z * C_DIM))[q];
            v[3] = ((const uint2*)(xhb + (size_t)ia.w * C_DIM))[q];
            v[4] = ((const uint2*)(xhb + (size_t)ib.x * C_DIM))[q];
            v[5] = ((const uint2*)(xhb + (size_t)ib.y * C_DIM))[q];
            v[6] = ((const uint2*)(xhb + (size_t)ib.z * C_DIM))[q];
            v[7] = ((const uint2*)(xhb + (size_t)ib.w * C_DIM))[q];
        }

        __syncthreads();   // sv[buf] visible; C(r-1) done reading so1

        // ---- Phase B: stage1 (o1[k*32+q] = sum_p w1[k,q,p] * v[k*32+p])
#pragma unroll
        for (int tt = 0; tt < 4; tt++) {
            const float4* vp = (const float4*)(&sv[buf][tt][kbase]);
            float o = 0.f;
#pragma unroll
            for (int p = 0; p < 8; p++) {
                float4 f = vp[p];
                o = fmaf(w1r[4*p+0], f.x, o);
                o = fmaf(w1r[4*p+1], f.y, o);
                o = fmaf(w1r[4*p+2], f.z, o);
                o = fmaf(w1r[4*p+3], f.w, o);
            }
            so1[tt][widx] = o;   // transposed: flat f=tid -> (l=f&7, r=f>>3)
        }
        __syncthreads();

        // ---- Phase C: stage2 + bias; write f32 t and bf16 shadow
#pragma unroll
        for (int tt = 0; tt < 4; tt++) {
            const float4* op = (const float4*)(&so1[tt][lbase]);
            float acc = br;
#pragma unroll
            for (int p = 0; p < 8; p++) {
                float4 f = op[p];
                acc = fmaf(w2r[4*p+0], f.x, acc);
                acc = fmaf(w2r[4*p+1], f.y, acc);
                acc = fmaf(w2r[4*p+2], f.z, acc);
                acc = fmaf(w2r[4*p+3], f.w, acc);
            }
            const size_t oi = (size_t)(tok0 + tt) * C_DIM + tid;
            g_t [oi] = acc;
            g_th[oi] = __float2bfloat16_rn(acc);
        }
        // no trailing barrier: next round's sv store targets the other buffer,
        // and barrier1 of the next round protects so1 against its next writer.
    }
}

// ---------------------------------------------------------------------------
// Kernel 2: rectify2 on t + rf. Warp-per-token, barrier-free, bf16 gathers.
// Lane owns 8 contiguous channels [8*lane, 8*lane+8): one uint4 (8 bf16) per
// neighbor per lane, two float4 for self/rf/out.
// ---------------------------------------------------------------------------
__global__ void __launch_bounds__(256) k2_rect_add(
        const float* __restrict__ rf,
        const int*   __restrict__ idx,
        float*       __restrict__ out) {
    const int lane = threadIdx.x & 31;
    const int warp = threadIdx.x >> 5;
    const int tok  = blockIdx.x * 8 + warp;     // grid = TOK_TOTAL/8
    const int b    = tok >> 13;
    const __nv_bfloat16* tb = g_th + ((size_t)b << 13) * C_DIM;

    // lanes 0-7 fetch this token's weights and neighbor indices
    float wv = 0.f; int iv = 0;
    if (lane < 8) {
        wv = g_w[(size_t)tok * 8 + lane];
        iv = idx[(size_t)tok * 8 + lane];
    }

    const float4* trow = (const float4*)(g_t + (size_t)tok * C_DIM);
    float4 s0 = trow[2*lane], s1 = trow[2*lane + 1];
    const float4* rrow = (const float4*)(rf + (size_t)tok * C_DIM);
    float4 r0 = rrow[2*lane], r1 = rrow[2*lane + 1];

    float4 a0 = make_float4(OME_W*s0.x + r0.x, OME_W*s0.y + r0.y,
                            OME_W*s0.z + r0.z, OME_W*s0.w + r0.w);
    float4 a1 = make_float4(OME_W*s1.x + r1.x, OME_W*s1.y + r1.y,
                            OME_W*s1.z + r1.z, OME_W*s1.w + r1.w);

#pragma unroll
    for (int k = 0; k < 8; k++) {
        float wk = __shfl_sync(0xFFFFFFFFu, wv, k);
        int   nb = __shfl_sync(0xFFFFFFFFu, iv, k);
        uint4 n = ((const uint4*)(tb + (size_t)nb * C_DIM))[lane];
        a0.x = fmaf(wk, bf_lo(n.x), a0.x);  a0.y = fmaf(wk, bf_hi(n.x), a0.y);
        a0.z = fmaf(wk, bf_lo(n.y), a0.z);  a0.w = fmaf(wk, bf_hi(n.y), a0.w);
        a1.x = fmaf(wk, bf_lo(n.z), a1.x);  a1.y = fmaf(wk, bf_hi(n.z), a1.y);
        a1.z = fmaf(wk, bf_lo(n.w), a1.z);  a1.w = fmaf(wk, bf_hi(n.w), a1.w);
    }

    float4* orow = (float4*)(out + (size_t)tok * C_DIM);
    orow[2*lane]     = a0;
    orow[2*lane + 1] = a1;
}

// ---------------------------------------------------------------------------
extern "C" void kernel_launch(void* const* d_in, const int* in_sizes, int n_in,
                              void* d_out, int out_size) {
    const float* x    = (const float*)d_in[0];
    const float* dist = (const float*)d_in[1];
    const int*   idx  = (const int*)  d_in[2];
    const float* rf   = (const float*)d_in[3];
    const float* w1   = (const float*)d_in[4];
    const float* w2   = (const float*)d_in[5];
    const float* bias = (const float*)d_in[6];
    float* out = (float*)d_out;

    // prep: 256 softmax blocks + 16384 conversion blocks (x -> bf16)
    prep_k<<<256 + (TOK_TOTAL * C_DIM / 4) / 256, 256>>>(dist, x);
    k1_rect_monarch<<<TOK_TOTAL / 32, 256>>>(x, idx, w1, w2, bias);
    k2_rect_add<<<TOK_TOTAL / 8, 256>>>(rf, idx, out);
}

// round 11
// speedup vs baseline: 1.1841x; 1.0248x over previous
#include <cuda_runtime.h>
#include <cuda_bf16.h>
#include <math.h>

// Problem constants: B=8, N=8192, C=256, K=8, nblocks=8, blk=32
#define TOK_TOTAL 65536          // B*N
#define N_TOK     8192
#define C_DIM     256
#define K_NB      8
#define EPS_W     0.05f
#define OME_W     0.95f

// Scratch (allocation-free rule: __device__ globals)
__device__ float          g_t [(size_t)TOK_TOTAL * C_DIM];  // 64 MB monarch out (f32)
__device__ __nv_bfloat16  g_th[(size_t)TOK_TOTAL * C_DIM];  // 32 MB bf16 shadow of t
__device__ __nv_bfloat16  g_xh[(size_t)TOK_TOTAL * C_DIM];  // 32 MB bf16 shadow of x
__device__ float          g_w [(size_t)TOK_TOTAL * K_NB];   // eps-scaled softmax weights

// bf16 -> f32 is exact: shift/mask into high mantissa bits (ALU pipe).
__device__ __forceinline__ float bf_lo(unsigned u) { return __uint_as_float(u << 16); }
__device__ __forceinline__ float bf_hi(unsigned u) { return __uint_as_float(u & 0xFFFF0000u); }

// ---- packed f32x2 helpers (FFMA2 is PTX-only; ptxas never auto-fuses) ------
union F2U { float2 f; unsigned long long u; };
__device__ __forceinline__ unsigned long long pk2(float x, float y) {
    F2U t; t.f.x = x; t.f.y = y; return t.u;
}
__device__ __forceinline__ void ffma2(unsigned long long& d,
                                      unsigned long long a,
                                      unsigned long long b) {
    asm("fma.rn.f32x2 %0, %1, %2, %0;" : "+l"(d) : "l"(a), "l"(b));
}
__device__ __forceinline__ float hsum2(unsigned long long v) {
    F2U t; t.u = v; return t.f.x + t.f.y;
}

// ---------------------------------------------------------------------------
// Kernel 0 (prep): blocks [0,256) compute eps*softmax(-distance);
// blocks [256, 256+16384) convert x (f32) -> g_xh (bf16).
// ---------------------------------------------------------------------------
__global__ void prep_k(const float* __restrict__ dist, const float* __restrict__ x) {
    if (blockIdx.x < 256) {
        int tok = blockIdx.x * blockDim.x + threadIdx.x;
        const float4* dp = (const float4*)(dist + (size_t)tok * K_NB);
        float4 a = dp[0], b4 = dp[1];
        float d[8] = {a.x, a.y, a.z, a.w, b4.x, b4.y, b4.z, b4.w};
        float e[8];
        float s = 0.f;
#pragma unroll
        for (int k = 0; k < 8; k++) { e[k] = __expf(-d[k]); s += e[k]; }
        float inv = EPS_W / s;
        float4* wp = (float4*)(g_w + (size_t)tok * K_NB);
        wp[0] = make_float4(e[0]*inv, e[1]*inv, e[2]*inv, e[3]*inv);
        wp[1] = make_float4(e[4]*inv, e[5]*inv, e[6]*inv, e[7]*inv);
    } else {
        size_t i = (size_t)(blockIdx.x - 256) * blockDim.x + threadIdx.x; // float4 id
        float4 f = __ldcs(&((const float4*)x)[i]);
        __nv_bfloat162 h0 = __float22bfloat162_rn(make_float2(f.x, f.y));
        __nv_bfloat162 h1 = __float22bfloat162_rn(make_float2(f.z, f.w));
        uint2 o;
        o.x = *reinterpret_cast<unsigned*>(&h0);
        o.y = *reinterpret_cast<unsigned*>(&h1);
        ((uint2*)g_xh)[i] = o;
    }
}

// ---------------------------------------------------------------------------
// Kernel 1: fused rectify1 + monarch, software pipelined, bf16 gathers,
// f32x2 packed math in the butterfly phases (pack-free: smem float4 loads
// reinterpret to u64 pairs; weights pre-packed once).
// 256 threads, 4 tokens/round, 8 rounds/block (32 tokens, 2048 blocks).
// ---------------------------------------------------------------------------
__global__ void __launch_bounds__(256, 2) k1_rect_monarch(
        const float* __restrict__ x,
        const int*   __restrict__ idx,
        const float* __restrict__ w1,
        const float* __restrict__ w2,
        const float* __restrict__ bias) {
    __shared__ __align__(16) float sv[2][4][C_DIM];
    __shared__ __align__(16) float so1[4][288];     // 8 * 36 padded

    const int tid = threadIdx.x;

    // Per-thread monarch weight rows, pre-packed as f32x2 along the
    // reduction dimension (p for stage1, r for stage2).
    unsigned long long w1p[16], w2p[16];
    {
        const float4* p1 = (const float4*)(w1 + (size_t)tid * 32);
#pragma unroll
        for (int i = 0; i < 8; i++) {
            float4 f = p1[i];
            w1p[2*i+0] = pk2(f.x, f.y);
            w1p[2*i+1] = pk2(f.z, f.w);
        }
        const float4* p2 = (const float4*)(w2 + (size_t)(tid & 7) * 1024 + (size_t)(tid >> 3) * 32);
#pragma unroll
        for (int i = 0; i < 8; i++) {
            float4 f = p2[i];
            w2p[2*i+0] = pk2(f.x, f.y);
            w2p[2*i+1] = pk2(f.z, f.w);
        }
    }
    const unsigned long long brp = pk2(bias[tid], 0.f);

    const int t = tid >> 6;          // token-in-round 0..3
    const int q = tid & 63;          // float4 / uint2 quad 0..63
    const int tokBlock = blockIdx.x * 32;            // 32 tokens per block
    const int b = tokBlock >> 13;                    // batch (N=8192)
    const __nv_bfloat16* xhb = g_xh + ((size_t)b << 13) * C_DIM; // bf16 gather base

    const int kbase = tid & 0xE0;                    // stage1 input block base
    const int widx  = (tid & 7) * 36 + (tid >> 3);   // transposed o1 slot
    const int lbase = (tid & 7) * 36;                // stage2 input row base

    // ---- Prefetch round 0: weights, idx, self (f32 streaming) + neighbors (bf16)
    float4 vself;
    uint2  v[8];
    float  swr[8];
    {
        const int tok = tokBlock + t;
        const float4* wp = (const float4*)(g_w + (size_t)tok * 8);
        float4 wa = wp[0], wb = wp[1];
        swr[0]=wa.x; swr[1]=wa.y; swr[2]=wa.z; swr[3]=wa.w;
        swr[4]=wb.x; swr[5]=wb.y; swr[6]=wb.z; swr[7]=wb.w;
        const int4* ip = (const int4*)(idx + (size_t)tok * 8);
        int4 ia = ip[0], ib = ip[1];
        vself = __ldcs(&((const float4*)(x + (size_t)tok * C_DIM))[q]);
        v[0] = ((const uint2*)(xhb + (size_t)ia.x * C_DIM))[q];
        v[1] = ((const uint2*)(xhb + (size_t)ia.y * C_DIM))[q];
        v[2] = ((const uint2*)(xhb + (size_t)ia.z * C_DIM))[q];
        v[3] = ((const uint2*)(xhb + (size_t)ia.w * C_DIM))[q];
        v[4] = ((const uint2*)(xhb + (size_t)ib.x * C_DIM))[q];
        v[5] = ((const uint2*)(xhb + (size_t)ib.y * C_DIM))[q];
        v[6] = ((const uint2*)(xhb + (size_t)ib.z * C_DIM))[q];
        v[7] = ((const uint2*)(xhb + (size_t)ib.w * C_DIM))[q];
    }

#pragma unroll 1
    for (int r = 0; r < 8; r++) {
        const int buf  = r & 1;
        const int tok0 = tokBlock + r * 4;

        // ---- Consume prefetched gather into the weighted sum; stage to smem
        {
            float4 acc = make_float4(OME_W*vself.x, OME_W*vself.y,
                                     OME_W*vself.z, OME_W*vself.w);
#pragma unroll
            for (int k = 0; k < 8; k++) {
                float wk = swr[k];
                acc.x = fmaf(wk, bf_lo(v[k].x), acc.x);
                acc.y = fmaf(wk, bf_hi(v[k].x), acc.y);
                acc.z = fmaf(wk, bf_lo(v[k].y), acc.z);
                acc.w = fmaf(wk, bf_hi(v[k].y), acc.w);
            }
            ((float4*)sv[buf][t])[q] = acc;
        }

        // ---- Issue next round's prefetch (overlaps with phases B+C below)
        if (r < 7) {
            const int tok = tok0 + 4 + t;
            const float4* wp = (const float4*)(g_w + (size_t)tok * 8);
            float4 wa = wp[0], wb = wp[1];
            swr[0]=wa.x; swr[1]=wa.y; swr[2]=wa.z; swr[3]=wa.w;
            swr[4]=wb.x; swr[5]=wb.y; swr[6]=wb.z; swr[7]=wb.w;
            const int4* ip = (const int4*)(idx + (size_t)tok * 8);
            int4 ia = ip[0], ib = ip[1];
            vself = __ldcs(&((const float4*)(x + (size_t)tok * C_DIM))[q]);
            v[0] = ((const uint2*)(xhb + (size_t)ia.x * C_DIM))[q];
            v[1] = ((const uint2*)(xhb + (size_t)ia.y * C_DIM))[q];
            v[2] = ((const uint2*)(xhb + (size_t)ia.z * C_DIM))[q];
            v[3] = ((const uint2*)(xhb + (size_t)ia.w * C_DIM))[q];
            v[4] = ((const uint2*)(xhb + (size_t)ib.x * C_DIM))[q];
            v[5] = ((const uint2*)(xhb + (size_t)ib.y * C_DIM))[q];
            v[6] = ((const uint2*)(xhb + (size_t)ib.z * C_DIM))[q];
            v[7] = ((const uint2*)(xhb + (size_t)ib.w * C_DIM))[q];
        }

        __syncthreads();   // sv[buf] visible; C(r-1) done reading so1

        // ---- Phase B: stage1, f32x2 along p. o1[k*32+q] = sum_p w1[k,q,p]*v
#pragma unroll
        for (int tt = 0; tt < 4; tt++) {
            const ulonglong2* vp = (const ulonglong2*)(&sv[buf][tt][kbase]);
            unsigned long long acc = 0ull;
#pragma unroll
            for (int p = 0; p < 8; p++) {
                ulonglong2 f = vp[p];          // LDS.128, pair-aliased
                ffma2(acc, w1p[2*p+0], f.x);
                ffma2(acc, w1p[2*p+1], f.y);
            }
            so1[tt][widx] = hsum2(acc);   // transposed: f=tid -> (l=f&7, r=f>>3)
        }
        __syncthreads();

        // ---- Phase C: stage2 + bias, f32x2 along r; write f32 t + bf16 shadow
#pragma unroll
        for (int tt = 0; tt < 4; tt++) {
            const ulonglong2* op = (const ulonglong2*)(&so1[tt][lbase]);
            unsigned long long acc = brp;
#pragma unroll
            for (int p = 0; p < 8; p++) {
                ulonglong2 f = op[p];
                ffma2(acc, w2p[2*p+0], f.x);
                ffma2(acc, w2p[2*p+1], f.y);
            }
            const float r2 = hsum2(acc);
            const size_t oi = (size_t)(tok0 + tt) * C_DIM + tid;
            __stcs(&g_t[oi], r2);                      // read-once stream
            g_th[oi] = __float2bfloat16_rn(r2);        // keep resident (gathered)
        }
        // no trailing barrier: next round's sv store targets the other buffer,
        // and barrier1 of the next round protects so1 against its next writer.
    }
}

// ---------------------------------------------------------------------------
// Kernel 2: rectify2 on t + rf. Warp-per-token, barrier-free, bf16 gathers.
// Streams (t self, rf, out) use evict-first hints so g_th stays L2-resident.
// ---------------------------------------------------------------------------
__global__ void __launch_bounds__(256) k2_rect_add(
        const float* __restrict__ rf,
        const int*   __restrict__ idx,
        float*       __restrict__ out) {
    const int lane = threadIdx.x & 31;
    const int warp = threadIdx.x >> 5;
    const int tok  = blockIdx.x * 8 + warp;     // grid = TOK_TOTAL/8
    const int b    = tok >> 13;
    const __nv_bfloat16* tb = g_th + ((size_t)b << 13) * C_DIM;

    // lanes 0-7 fetch this token's weights and neighbor indices
    float wv = 0.f; int iv = 0;
    if (lane < 8) {
        wv = g_w[(size_t)tok * 8 + lane];
        iv = idx[(size_t)tok * 8 + lane];
    }

    const float4* trow = (const float4*)(g_t + (size_t)tok * C_DIM);
    float4 s0 = __ldcs(&trow[2*lane]), s1 = __ldcs(&trow[2*lane + 1]);
    const float4* rrow = (const float4*)(rf + (size_t)tok * C_DIM);
    float4 r0 = __ldcs(&rrow[2*lane]), r1 = __ldcs(&rrow[2*lane + 1]);

    float4 a0 = make_float4(OME_W*s0.x + r0.x, OME_W*s0.y + r0.y,
                            OME_W*s0.z + r0.z, OME_W*s0.w + r0.w);
    float4 a1 = make_float4(OME_W*s1.x + r1.x, OME_W*s1.y + r1.y,
                            OME_W*s1.z + r1.z, OME_W*s1.w + r1.w);

#pragma unroll
    for (int k = 0; k < 8; k++) {
        float wk = __shfl_sync(0xFFFFFFFFu, wv, k);
        int   nb = __shfl_sync(0xFFFFFFFFu, iv, k);
        uint4 n = ((const uint4*)(tb + (size_t)nb * C_DIM))[lane];
        a0.x = fmaf(wk, bf_lo(n.x), a0.x);  a0.y = fmaf(wk, bf_hi(n.x), a0.y);
        a0.z = fmaf(wk, bf_lo(n.y), a0.z);  a0.w = fmaf(wk, bf_hi(n.y), a0.w);
        a1.x = fmaf(wk, bf_lo(n.z), a1.x);  a1.y = fmaf(wk, bf_hi(n.z), a1.y);
        a1.z = fmaf(wk, bf_lo(n.w), a1.z);  a1.w = fmaf(wk, bf_hi(n.w), a1.w);
    }

    float4* orow = (float4*)(out + (size_t)tok * C_DIM);
    __stcs(&orow[2*lane],     a0);
    __stcs(&orow[2*lane + 1], a1);
}

// ---------------------------------------------------------------------------
extern "C" void kernel_launch(void* const* d_in, const int* in_sizes, int n_in,
                              void* d_out, int out_size) {
    const float* x    = (const float*)d_in[0];
    const float* dist = (const float*)d_in[1];
    const int*   idx  = (const int*)  d_in[2];
    const float* rf   = (const float*)d_in[3];
    const float* w1   = (const float*)d_in[4];
    const float* w2   = (const float*)d_in[5];
    const float* bias = (const float*)d_in[6];
    float* out = (float*)d_out;

    // prep: 256 softmax blocks + 16384 conversion blocks (x -> bf16)
    prep_k<<<256 + (TOK_TOTAL * C_DIM / 4) / 256, 256>>>(dist, x);
    k1_rect_monarch<<<TOK_TOTAL / 32, 256>>>(x, idx, w1, w2, bias);
    k2_rect_add<<<TOK_TOTAL / 8, 256>>>(rf, idx, out);
}